// round 6
// baseline (speedup 1.0000x reference)
#include <cuda_runtime.h>
#include <float.h>

// ChamferDist (adv->ori): loss = mean_b( w_b * mean_k( min_j ||adv[bk]-ori[bj]||^2 ) )
//
// min_j dist = a2_k + min_j (b2_j - 2 a_k.b_j).
// R6: same inner loop as R5 (2 LDS.128 + 12 FFMA2 + 8 FMNMX per ori-pair for
// 4 adv pts/thread), but grid-limited occupancy fixed:
//   JS=16 (JCHUNK=256) -> grid = B*16*ktiles = 512 CTAs @ B=8,K=4096
//   __launch_bounds__(256,3) -> <=64 regs, 3 CTAs/SM, ~5.5 warps/SMSP.
// Combine: scratch[point][16] partial mins; per-(b,ktile) counter -> group's
// last CTA min-combines + weighted sum; global counter -> final scalar.
// Single launch, deterministic (fixed-order reductions), graph-replay safe.

#define CD_THREADS 256
#define CD_PTS     4
#define CD_JS      16
#define CD_KCHUNK  1024          // CD_THREADS * CD_PTS
#define CD_JCHUNK  256
#define CD_PAIRS   128           // CD_JCHUNK / 2
#define CD_MAX_SCRATCH (1 << 21) // floats (8 MB)
#define CD_MAX_GROUPS  1024

__device__ float        g_cd_scratch[CD_MAX_SCRATCH];
__device__ float        g_cd_group[CD_MAX_GROUPS];
__device__ unsigned int g_cd_tile_count[CD_MAX_GROUPS];
__device__ unsigned int g_cd_final_count;

__device__ __forceinline__ unsigned long long pack_dup(float v) {
    unsigned long long r;
    asm("mov.b64 %0, {%1, %1};" : "=l"(r) : "f"(v));
    return r;
}
__device__ __forceinline__ unsigned long long fma2(unsigned long long a,
                                                   unsigned long long b,
                                                   unsigned long long c) {
    unsigned long long d;
    asm("fma.rn.f32x2 %0, %1, %2, %3;" : "=l"(d) : "l"(a), "l"(b), "l"(c));
    return d;
}

__global__ __launch_bounds__(CD_THREADS, 3)
void chamfer_main_kernel(const float* __restrict__ adv,
                         const float* __restrict__ ori,
                         const float* __restrict__ w,
                         float* __restrict__ out,
                         int B, int K, int ktiles, float scale) {
    __shared__ float4 sXY[CD_PAIRS];
    __shared__ float4 sZW[CD_PAIRS];
    __shared__ float  red[CD_THREADS / 32];
    __shared__ bool   sFlag;

    const int tid = threadIdx.x;
    const int kt  = blockIdx.x % ktiles;
    const int rem = blockIdx.x / ktiles;
    const int js  = rem % CD_JS;
    const int b   = rem / CD_JS;
    const int ngroups = B * ktiles;
    const int gid = b * ktiles + kt;

    // ---- Fill smem with this CTA's ori j-chunk (pair layout) ----
    const int j0g = js * CD_JCHUNK;
    int cl = K - j0g;
    if (cl > CD_JCHUNK) cl = CD_JCHUNK;
    if (cl < 0) cl = 0;
    const int pairsPad = (cl + 1) >> 1;

    const float* __restrict__ orib = ori + (size_t)b * K * 3;
    if (tid < pairsPad) {
        const int p  = tid;
        const int j0 = 2 * p;
        const int j1 = (2 * p + 1 < cl) ? (2 * p + 1) : (cl - 1);
        const float x0 = orib[(j0g + j0) * 3 + 0];
        const float y0 = orib[(j0g + j0) * 3 + 1];
        const float z0 = orib[(j0g + j0) * 3 + 2];
        const float x1 = orib[(j0g + j1) * 3 + 0];
        const float y1 = orib[(j0g + j1) * 3 + 1];
        const float z1 = orib[(j0g + j1) * 3 + 2];
        sXY[p] = make_float4(-2.0f * x0, -2.0f * x1, -2.0f * y0, -2.0f * y1);
        sZW[p] = make_float4(-2.0f * z0, -2.0f * z1,
                             x0 * x0 + y0 * y0 + z0 * z0,
                             x1 * x1 + y1 * y1 + z1 * z1);
    }
    __syncthreads();

    // ---- 4 adv points per thread ----
    int   kk[CD_PTS];
    float a2[CD_PTS];
    unsigned long long axx[CD_PTS], ayy[CD_PTS], azz[CD_PTS];
#pragma unroll
    for (int u = 0; u < CD_PTS; ++u) {
        const int k = kt * CD_KCHUNK + tid + u * CD_THREADS;
        kk[u] = k;
        float x = 0.f, y = 0.f, z = 0.f;
        if (k < K) {
            const float* __restrict__ a = adv + ((size_t)b * K + k) * 3;
            x = a[0]; y = a[1]; z = a[2];
        }
        a2[u]  = x * x + y * y + z * z;
        axx[u] = pack_dup(x); ayy[u] = pack_dup(y); azz[u] = pack_dup(z);
    }

    float mlo[CD_PTS], mhi[CD_PTS];
#pragma unroll
    for (int u = 0; u < CD_PTS; ++u) { mlo[u] = FLT_MAX; mhi[u] = FLT_MAX; }

    const ulonglong2* __restrict__ pXY = (const ulonglong2*)sXY;
    const ulonglong2* __restrict__ pZW = (const ulonglong2*)sZW;

#pragma unroll 4
    for (int p = 0; p < pairsPad; ++p) {
        const ulonglong2 A = pXY[p];   // (x0,x1) , (y0,y1)
        const ulonglong2 Z = pZW[p];   // (z0,z1) , (b2_0,b2_1)
#pragma unroll
        for (int u = 0; u < CD_PTS; ++u) {
            union { unsigned long long u64; float2 f2; } t;
            t.u64 = fma2(azz[u], Z.x, Z.y);
            t.u64 = fma2(ayy[u], A.y, t.u64);
            t.u64 = fma2(axx[u], A.x, t.u64);
            mlo[u] = fminf(mlo[u], t.f2.x);
            mhi[u] = fminf(mhi[u], t.f2.y);
        }
    }

    // ---- Write partial mins (a2 folded in) ----
#pragma unroll
    for (int u = 0; u < CD_PTS; ++u) {
        if (kk[u] < K) {
            g_cd_scratch[((size_t)b * K + kk[u]) * CD_JS + js] =
                fminf(mlo[u], mhi[u]) + a2[u];
        }
    }

    // ---- Per-(b,ktile) group combine by the group's last CTA ----
    __threadfence();
    if (tid == 0) {
        const unsigned int c = atomicAdd(&g_cd_tile_count[gid], 1u);
        sFlag = (c == (unsigned int)(CD_JS - 1));
    }
    __syncthreads();
    if (!sFlag) return;
    __threadfence();

    {
        const int kbase = kt * CD_KCHUNK;
        int npts = K - kbase;
        if (npts > CD_KCHUNK) npts = CD_KCHUNK;
        const float* __restrict__ base =
            g_cd_scratch + ((size_t)b * K + kbase) * CD_JS;
        float s = 0.0f;
        for (int i = tid; i < npts; i += CD_THREADS) {
            const float4* __restrict__ pp = (const float4*)(base + (size_t)i * CD_JS);
            float mv = FLT_MAX;
#pragma unroll
            for (int q = 0; q < CD_JS / 4; ++q) {
                const float4 v = pp[q];
                mv = fminf(mv, fminf(fminf(v.x, v.y), fminf(v.z, v.w)));
            }
            s += mv;
        }
        const int lane = tid & 31, wid = tid >> 5;
#pragma unroll
        for (int off = 16; off > 0; off >>= 1)
            s += __shfl_down_sync(0xffffffffu, s, off);
        if (lane == 0) red[wid] = s;
        __syncthreads();
        if (tid == 0) {
            float v = 0.0f;
#pragma unroll
            for (int i = 0; i < CD_THREADS / 32; ++i) v += red[i];
            g_cd_group[gid] = v * w[b];
            g_cd_tile_count[gid] = 0u;   // reset for graph replay
            __threadfence();
            const unsigned int c = atomicAdd(&g_cd_final_count, 1u);
            sFlag = (c == (unsigned int)(ngroups - 1));
        }
        __syncthreads();
        if (!sFlag) return;

        // ---- Final: sum the (<=64) group sums, fixed order ----
        if (tid == 0) {
            __threadfence();
            float v = 0.0f;
#pragma unroll 8
            for (int i = 0; i < ngroups; ++i) v += g_cd_group[i];
            out[0] = v * scale;
            g_cd_final_count = 0u;       // reset for graph replay
        }
    }
}

extern "C" void kernel_launch(void* const* d_in, const int* in_sizes, int n_in,
                              void* d_out, int out_size) {
    const float* adv = (const float*)d_in[0];   // [B, K, 3] float32
    const float* ori = (const float*)d_in[1];   // [B, K, 3] float32
    const float* w   = (const float*)d_in[2];   // [B]       float32
    float* out = (float*)d_out;                 // scalar float32

    const int B = in_sizes[2];
    const int K = in_sizes[0] / (3 * B);

    const int ktiles = (K + CD_KCHUNK - 1) / CD_KCHUNK;
    const int blocks = B * CD_JS * ktiles;      // 8*16*4 = 512 @ B=8,K=4096

    const float scale = 1.0f / ((float)B * (float)K);
    chamfer_main_kernel<<<blocks, CD_THREADS>>>(adv, ori, w, out,
                                                B, K, ktiles, scale);
}